// round 16
// baseline (speedup 1.0000x reference)
#include <cuda_runtime.h>
#include <cuda_fp16.h>
#include <math.h>
#include <stdint.h>

#define BB 32
#define LL 256
#define DD 128
#define GG 512

__device__ float g_xw  [BB*LL*GG];   // x @ Wr + br
// fp16, transposed, rank-sliced, gate-permuted weights:
// c = g*32 + jj  <->  global col = g*128 + r*32 + jj
__device__ __align__(16) __half g_W2Th[4*128*256];  // k: 0..127 Uw, 128..255 F
__device__ __align__(16) __half g_ETh [4*128*128];  // E = Wc_top@Ww
__device__ __align__(16) __half g_URh [4*128*128];  // Ur
__device__ float g_cvec[GG];                        // bc@Ww + bw

__device__ __forceinline__ float hsig(float x) {
    return fminf(fmaxf(0.2f*x + 0.5f, 0.0f), 1.0f);
}
__device__ __forceinline__ float tanh_fast(float x) {
    float e = __expf(fminf(2.0f*x, 80.0f));
    return 1.0f - __fdividef(2.0f, e + 1.0f);
}
__device__ __forceinline__ uint32_t smem_u32(const void* p) {
    uint32_t a;
    asm("{ .reg .u64 t; cvta.to.shared.u64 t, %1; cvt.u32.u64 %0, t; }" : "=r"(a) : "l"(p));
    return a;
}
__device__ __forceinline__ uint32_t ctarank() {
    uint32_t r; asm("mov.u32 %0, %%cluster_ctarank;" : "=r"(r)); return r;
}
__device__ __forceinline__ uint32_t mapa_u32(uint32_t a, uint32_t rk) {
    uint32_t o; asm("mapa.shared::cluster.u32 %0, %1, %2;" : "=r"(o) : "r"(a), "r"(rk)); return o;
}
__device__ __forceinline__ void mbar_init(uint32_t a, uint32_t cnt) {
    asm volatile("mbarrier.init.shared.b64 [%0], %1;" :: "r"(a), "r"(cnt) : "memory");
}
__device__ __forceinline__ void mbar_arrive_expect(uint32_t a, uint32_t tx) {
    asm volatile("mbarrier.arrive.expect_tx.shared.b64 _, [%0], %1;" :: "r"(a), "r"(tx) : "memory");
}
__device__ __forceinline__ void mbar_wait(uint32_t a, uint32_t parity) {
    uint32_t done;
    asm volatile("{\n\t.reg .pred p;\n\t"
        "mbarrier.try_wait.parity.acquire.cta.shared::cta.b64 p, [%1], %2;\n\t"
        "selp.b32 %0, 1, 0, p;\n\t}" : "=r"(done) : "r"(a), "r"(parity) : "memory");
    if (!done) {
        asm volatile("{\n\t.reg .pred P1;\n\tWL_%=:\n\t"
            "mbarrier.try_wait.parity.acquire.cta.shared::cta.b64 P1, [%0], %1, 0x989680;\n\t"
            "@P1 bra.uni WD_%=;\n\tbra.uni WL_%=;\n\tWD_%=:\n\t}"
            :: "r"(a), "r"(parity) : "memory");
    }
}
__device__ __forceinline__ void st_async_f32(uint32_t ra, float v, uint32_t rmb) {
    asm volatile("st.async.shared::cluster.mbarrier::complete_tx::bytes.b32 [%0], %1, [%2];"
                 :: "r"(ra), "r"(__float_as_uint(v)), "r"(rmb) : "memory");
}
__device__ __forceinline__ void st_async_f64(uint32_t ra, float a, float b, uint32_t rmb) {
    unsigned long long v = ((unsigned long long)__float_as_uint(b) << 32) | __float_as_uint(a);
    asm volatile("st.async.shared::cluster.mbarrier::complete_tx::bytes.b64 [%0], %1, [%2];"
                 :: "r"(ra), "l"(v), "r"(rmb) : "memory");
}
#define CLUSTER_SYNC_() do { \
    asm volatile("barrier.cluster.arrive.aligned;" ::: "memory"); \
    asm volatile("barrier.cluster.wait.aligned;" ::: "memory"); } while (0)
#define BAR_ARRIVE(id,cnt) asm volatile("bar.arrive %0, %1;" :: "r"(id), "r"(cnt) : "memory")
#define BAR_SYNC(id,cnt)   asm volatile("bar.sync %0, %1;"   :: "r"(id), "r"(cnt) : "memory")

// consumer parity for o_j arriving via hr ring slot j%3 (first bar uses: slot0:j=3, slot1:j=1, slot2:j=2)
__device__ __forceinline__ int hr_par(int j) {
    int s = j % 3;
    int base = (s == 0) ? 3 : s;
    return ((j - base) / 3) & 1;
}

__device__ __forceinline__ void red8_store(float* p, int lane, float* dst) {
    #pragma unroll
    for (int ofs = 16, n = 8; ofs >= 4; ofs >>= 1, n >>= 1) {
        int half = n >> 1;
        bool side = (lane & ofs) != 0;
        #pragma unroll
        for (int i = 0; i < 4; i++) {
            if (i < half) {
                float send = side ? p[i] : p[i + half];
                float recv = __shfl_xor_sync(0xffffffffu, send, ofs);
                p[i] = (side ? p[i + half] : p[i]) + recv;
            }
        }
    }
    p[0] += __shfl_xor_sync(0xffffffffu, p[0], 2);
    p[0] += __shfl_xor_sync(0xffffffffu, p[0], 1);
    if ((lane & 3) == 0) dst[(lane >> 2) & 7] = p[0];
}

__device__ __forceinline__ float dot4_h(uint2 w, float4 hv) {
    float2 a = __half22float2(*reinterpret_cast<__half2*>(&w.x));
    float2 b = __half22float2(*reinterpret_cast<__half2*>(&w.y));
    return hv.x*a.x + hv.y*a.y + hv.z*b.x + hv.w*b.y;
}

// ---------------- GEMM: C[M,512] = A[M,128] @ W[128,512] + bias ------------
__global__ void __launch_bounds__(256) gemm_k128_n512(
        const float* __restrict__ A, const float* __restrict__ W,
        const float* __restrict__ bias, float* __restrict__ C)
{
    __shared__ __align__(16) float As[64][68];
    __shared__ __align__(16) float Ws[64][64];
    int tid = threadIdx.x, tx = tid & 15, ty = tid >> 4;
    int n0 = blockIdx.x * 64;
    long r0 = (long)blockIdx.y * 64;
    float acc[4][4] = {};
    for (int kc = 0; kc < 128; kc += 64) {
        #pragma unroll
        for (int i = 0; i < 4; i++) {
            int f = tid + i*256, row = f >> 4, c4 = (f & 15) * 4;
            *reinterpret_cast<float4*>(&As[row][c4]) =
                *reinterpret_cast<const float4*>(A + (r0 + row)*128 + kc + c4);
            *reinterpret_cast<float4*>(&Ws[row][c4]) =
                *reinterpret_cast<const float4*>(W + (long)(kc + row)*GG + n0 + c4);
        }
        __syncthreads();
        #pragma unroll
        for (int k = 0; k < 64; k++) {
            float4 wv = *reinterpret_cast<const float4*>(&Ws[k][tx*4]);
            #pragma unroll
            for (int i = 0; i < 4; i++) {
                float a = As[ty*4 + i][k];
                acc[i][0] += a*wv.x; acc[i][1] += a*wv.y;
                acc[i][2] += a*wv.z; acc[i][3] += a*wv.w;
            }
        }
        __syncthreads();
    }
    int col = n0 + tx*4;
    float4 bv = *reinterpret_cast<const float4*>(bias + col);
    #pragma unroll
    for (int i = 0; i < 4; i++) {
        float4 o;
        o.x = acc[i][0] + bv.x; o.y = acc[i][1] + bv.y;
        o.z = acc[i][2] + bv.z; o.w = acc[i][3] + bv.w;
        *reinterpret_cast<float4*>(C + (r0 + ty*4 + i)*GG + col) = o;
    }
}

// ---------------- prep: fp16 transposed W2T/ET/URt, cvec -------------------
__global__ void __launch_bounds__(512) prep_EF(
        const float* __restrict__ Wc, const float* __restrict__ Ww,
        const float* __restrict__ bc, const float* __restrict__ bw,
        const float* __restrict__ Uw, const float* __restrict__ Ur)
{
    __shared__ float st[DD], sb[DD], sc[DD];
    int d = blockIdx.x, j = threadIdx.x;
    if (j < DD) { st[j] = Wc[d*DD + j]; sb[j] = Wc[(DD + d)*DD + j]; sc[j] = bc[j]; }
    __syncthreads();
    float e = 0.f, f = 0.f, cv = 0.f;
    #pragma unroll 8
    for (int c = 0; c < DD; c++) {
        float w = Ww[c*GG + j];
        e += st[c]*w; f += sb[c]*w; cv += sc[c]*w;
    }
    int g = j >> 7, r = (j >> 5) & 3, jj = j & 31;
    int c = g*32 + jj;
    g_W2Th[(r*128 + c)*256 + d]       = __float2half(Uw[d*GG + j]);
    g_W2Th[(r*128 + c)*256 + 128 + d] = __float2half(f);
    g_ETh [(r*128 + c)*128 + d]       = __float2half(e);
    g_URh [(r*128 + c)*128 + d]       = __float2half(Ur[d*GG + j]);
    if (d == 0) g_cvec[j] = cv + bw[j];
}

// ---------------- fused kernel: reader 2 ahead + writer, min-critical-path -
// smem float offsets
#define M_W2   0        // UwF half [128][256]   (16384)
#define M_EU   16384    // E half [128][128]     (8192)
#define M_UR   24576    // Ur half [128][128]    (8192)
#define M_PA   32768    // [16][128]             (2048)
#define M_CVEC 34816    // [128]
#define M_ZS   34944    // [128]
#define M_ZSR  35072    // [128]
#define M_XWR  35200    // [2][128]
#define M_EE   35456    // [64]
#define M_ONX2 35520    // [2][32]
#define M_COMM 35584    // comm block below (even offset)
// comm block (float offsets relative to M_COMM)
#define CO_MRTB 0       // [4][128]
#define CO_HRB  512     // [3][128] o ring
#define CO_HWB  896     // [2][128] h ring
#define CO_SB   1152    // [4]
#define CO_HOB  1156    // [4]
#define CO_BMRT 1160    // 1 bar
#define CO_BHW  1162    // 2 bars
#define CO_BHR  1166    // 3 bars
#define C_TOT   1172
#define M_TOT  (M_COMM + C_TOT)

__global__ void __launch_bounds__(512, 1) __cluster_dims__(4, 1, 1)
fused_kernel(const float* __restrict__ x, float* __restrict__ out)
{
    extern __shared__ __align__(16) float sm[];
    float* PA   = sm + M_PA;
    float* CVEC = sm + M_CVEC;
    float* ZS   = sm + M_ZS;
    float* ZSR  = sm + M_ZSR;
    float* XWR  = sm + M_XWR;
    float* EE   = sm + M_EE;
    float* ONX2 = sm + M_ONX2;
    float* CM   = sm + M_COMM;
    float* MRTB = CM + CO_MRTB;
    float* HRB  = CM + CO_HRB;
    float* HWB  = CM + CO_HWB;
    float* SB   = CM + CO_SB;
    float* HOB  = CM + CO_HOB;
    const uint2* W2u = reinterpret_cast<const uint2*>(sm + M_W2);  // 64 uint2/col
    const uint2* EUu = reinterpret_cast<const uint2*>(sm + M_EU);  // 32 uint2/col
    const uint2* URu = reinterpret_cast<const uint2*>(sm + M_UR);  // 32 uint2/col

    int tid = threadIdx.x, lane = tid & 31, warp = tid >> 5;
    uint32_t rank = ctarank();
    int b = blockIdx.x >> 2;
    int r0 = warp*4;

    uint32_t mrt_barL = smem_u32(CM + CO_BMRT);
    uint32_t hwbarL[2] = { smem_u32(CM + CO_BHW), smem_u32(CM + CO_BHW + 2) };
    uint32_t hrbarL[3] = { smem_u32(CM + CO_BHR), smem_u32(CM + CO_BHR + 2),
                           smem_u32(CM + CO_BHR + 4) };
    if (tid == 0) {
        mbar_init(mrt_barL, 1);
        mbar_init(hwbarL[0], 1); mbar_init(hwbarL[1], 1);
        mbar_init(hrbarL[0], 1); mbar_init(hrbarL[1], 1); mbar_init(hrbarL[2], 1);
    }

    const float* xwb = g_xw + (long)b*LL*GG;

    // weight slices -> smem (fp16)
    {
        uint4* dst = reinterpret_cast<uint4*>(sm + M_W2);
        const uint4* src = reinterpret_cast<const uint4*>(g_W2Th) + (long)rank*4096;
        for (int i = tid; i < 4096; i += 512) dst[i] = src[i];
        uint4* dstE = reinterpret_cast<uint4*>(sm + M_EU);
        const uint4* srcE = reinterpret_cast<const uint4*>(g_ETh) + (long)rank*2048;
        for (int i = tid; i < 2048; i += 512) dstE[i] = srcE[i];
        uint4* dstU = reinterpret_cast<uint4*>(sm + M_UR);
        const uint4* srcU = reinterpret_cast<const uint4*>(g_URh) + (long)rank*2048;
        for (int i = tid; i < 2048; i += 512) dstU[i] = srcU[i];
    }
    // mem slice -> REGISTERS: warp owns rows r0..r0+3 (global rows rank*64+..)
    float4 m[4];
    {
        const float* xb = x + ((long)b*LL + rank*64)*DD;
        #pragma unroll
        for (int li = 0; li < 4; li++)
            m[li] = *reinterpret_cast<const float4*>(xb + (r0 + li)*DD + lane*4);
    }
    if (tid < 256) HWB[tid] = 0.f;
    if (tid < 128) {
        // reader step 0 (h=0): o_0 full vector (computed locally by every CTA)
        float zi = xwb[tid], zg = xwb[256 + tid], zo = xwb[384 + tid];
        float c0 = hsig(zi) * tanh_fast(zg);
        float o0 = hsig(zo) * tanh_fast(c0);
        HRB[tid] = o0;         // ring slot 0
        ZSR[tid] = c0;         // stash c_r(0) for warp2 pickup
        CVEC[tid] = g_cvec[(tid >> 5)*128 + rank*32 + (tid & 31)];
    } else if (tid < 256) {
        int i = tid - 128;     // XWR slot 0 = xw step 2 (read by warp2 at t=0)
        XWR[i] = xwb[2*GG + (i >> 5)*128 + rank*32 + (i & 31)];
    }
    float cst_w = 0.f, cst_r = 0.f;
    __syncthreads();
    CLUSTER_SYNC_();

    // single comm-base address per peer (q=3 -> self)
    uint32_t r_cb[4];
    #pragma unroll
    for (int q = 0; q < 4; q++)
        r_cb[q] = mapa_u32(smem_u32(CM), (rank + 1 + q) & 3);

    float4* PA4  = reinterpret_cast<float4*>(PA);
    const float2* PA2 = reinterpret_cast<const float2*>(PA);
    const float4* MRTB4 = reinterpret_cast<const float4*>(MRTB);

    // ---- bootstrap: reader step 1 -> o_1 (ring slot 1) --------------------
    if (tid == 0) mbar_arrive_expect(hrbarL[1], 512);
    {
        float4 o0v = reinterpret_cast<const float4*>(HRB)[lane];
        float accB[8];
        #pragma unroll
        for (int i = 0; i < 8; i++)
            accB[i] = dot4_h(URu[(warp*8 + i)*32 + lane], o0v);
        red8_store(accB, lane, ZS + warp*8);
    }
    __syncthreads();
    if (warp == 2) {
        int j = lane;
        cst_r = ZSR[rank*32 + j];              // c_r(0)
        float i_ = hsig (ZS[j]      + xwb[GG + 0*128 + rank*32 + j]);
        float f_ = hsig (ZS[32 + j] + xwb[GG + 1*128 + rank*32 + j]);
        float g_ = tanh_fast(ZS[64 + j] + xwb[GG + 2*128 + rank*32 + j]);
        float o_ = hsig (ZS[96 + j] + xwb[GG + 3*128 + rank*32 + j]);
        cst_r = f_*cst_r + i_*g_;
        float hr = o_ * tanh_fast(cst_r);      // o_1 local dims
        ONX2[32 + j] = hr;                     // ONX slot 1
        float hn = __shfl_xor_sync(0xffffffffu, hr, 1);
        if ((j & 1) == 0) {
            #pragma unroll
            for (int q = 0; q < 4; q++)
                st_async_f64(r_cb[q] + (CO_HRB + 128u + rank*32u + (uint32_t)j)*4u,
                             hr, hn, r_cb[q] + CO_BHR*4u + 1u*8u);
        }
    }
    // ---- initial scores s_0 from o_0 (registers) -> EE, PA ----------------
    {
        float4 ov = reinterpret_cast<const float4*>(HRB)[lane];
        float pr_[4];
        #pragma unroll
        for (int li = 0; li < 4; li++)
            pr_[li] = m[li].x*ov.x + m[li].y*ov.y + m[li].z*ov.z + m[li].w*ov.w;
        #pragma unroll
        for (int ofs = 16, n = 4; ofs >= 8; ofs >>= 1, n >>= 1) {
            int half = n >> 1;
            bool side = (lane & ofs) != 0;
            #pragma unroll
            for (int i = 0; i < 2; i++) {
                if (i < half) {
                    float send = side ? pr_[i] : pr_[i + half];
                    float recv = __shfl_xor_sync(0xffffffffu, send, ofs);
                    pr_[i] = (side ? pr_[i + half] : pr_[i]) + recv;
                }
            }
        }
        pr_[0] += __shfl_xor_sync(0xffffffffu, pr_[0], 4);
        pr_[0] += __shfl_xor_sync(0xffffffffu, pr_[0], 2);
        pr_[0] += __shfl_xor_sync(0xffffffffu, pr_[0], 1);
        if ((lane & 7) == 0) EE[r0 + ((lane >> 3) & 3)] = __expf(pr_[0]);
        __syncwarp();
        float4 pacc = make_float4(0.f, 0.f, 0.f, 0.f);
        #pragma unroll
        for (int li = 0; li < 4; li++) {
            float e = EE[r0 + li];
            pacc.x = fmaf(e, m[li].x, pacc.x);
            pacc.y = fmaf(e, m[li].y, pacc.y);
            pacc.z = fmaf(e, m[li].z, pacc.z);
            pacc.w = fmaf(e, m[li].w, pacc.w);
        }
        PA4[warp*32 + lane] = pacc;
    }
    __syncthreads();

    for (int t = 0; t < LL; t++) {
        int sl0 = t % 3, sl1 = (t + 1) % 3, sl2 = (t + 2) % 3;
        int bufw = t & 1;
        if (tid == 0) {
            mbar_arrive_expect(mrt_barL, 2064);          // 4 x (512 + 4)
            mbar_arrive_expect(hwbarL[bufw], 528);       // 4 x (128 + 4)
            if (t < LL - 1) mbar_arrive_expect(hrbarL[sl2], 512);
        }
        // ---- o_{t+1} arrival (sent an iteration ago -> ~free)
        mbar_wait(hrbarL[sl1], hr_par(t + 1));

        // ---- sends + prefetch
        if (tid < 64) {
            float2 p = make_float2(0.f, 0.f);
            #pragma unroll
            for (int w = 0; w < 16; w++) {
                float2 v = PA2[w*64 + tid];
                p.x += v.x; p.y += v.y;
            }
            #pragma unroll
            for (int q = 0; q < 4; q++)
                st_async_f64(r_cb[q] + (CO_MRTB + rank*128u + 2u*(uint32_t)tid)*4u,
                             p.x, p.y, r_cb[q] + CO_BMRT*4u);
        } else if (tid >= 96 && tid < 128) {
            float v = EE[lane] + EE[32 + lane];
            #pragma unroll
            for (int o = 16; o > 0; o >>= 1) v += __shfl_xor_sync(0xffffffffu, v, o);
            if (lane == 0) {
                #pragma unroll
                for (int q = 0; q < 4; q++)
                    st_async_f32(r_cb[q] + (CO_SB + rank)*4u, v, r_cb[q] + CO_BMRT*4u);
            }
        } else if (tid >= 128 && tid < 192) {
            int i = (tid - 128)*2;
            int tn3 = (t + 3 < LL) ? t + 3 : LL - 1;
            int s = (t + 3) & 1;
            XWR[s*128 + i]     = xwb[tn3*GG + (i >> 5)*128 + rank*32 + (i & 31)];
            XWR[s*128 + i + 1] = xwb[tn3*GG + ((i+1) >> 5)*128 + rank*32 + ((i+1) & 31)];
        }
        // ---- GEMVs: reader (o_{t+1}), writer Uw(h_w) + E(o_t)
        float accR[8], acc[8];
        {
            float4 ov1 = reinterpret_cast<const float4*>(HRB + sl1*128)[lane];
            float4 ov0 = reinterpret_cast<const float4*>(HRB + sl0*128)[lane];
            float4 hwv = reinterpret_cast<const float4*>(HWB + (bufw ^ 1)*128)[lane];
            #pragma unroll
            for (int i = 0; i < 8; i++) {
                int c = warp*8 + i;
                accR[i] = dot4_h(URu[c*32 + lane], ov1);
                acc[i]  = dot4_h(W2u[c*64 + lane], hwv) + dot4_h(EUu[c*32 + lane], ov0);
            }
            red8_store(accR, lane, ZSR + warp*8);
        }
        // ---- F-half GEMV on unnormalized P (deferred normalization)
        mbar_wait(mrt_barL, t & 1);
        float inv = 1.0f / (SB[0] + SB[1] + SB[2] + SB[3]);
        {
            float4 mvP = MRTB4[lane];
            float4 v1 = MRTB4[32 + lane], v2 = MRTB4[64 + lane], v3 = MRTB4[96 + lane];
            mvP.x += v1.x + v2.x + v3.x;
            mvP.y += v1.y + v2.y + v3.y;
            mvP.z += v1.z + v2.z + v3.z;
            mvP.w += v1.w + v2.w + v3.w;
            #pragma unroll
            for (int i = 0; i < 8; i++) {
                float f = dot4_h(W2u[(warp*8 + i)*64 + 32 + lane], mvP);
                acc[i] = fmaf(f, inv, acc[i]);
            }
            red8_store(acc, lane, ZS + warp*8);
        }
        // ---- named barrier: 14 warps arrive, warps 0 & 2 sync
        if (warp == 0 || warp == 2) BAR_SYNC(1, 512); else BAR_ARRIVE(1, 512);

        // ---- warp0: writer gates + h/ho sends
        if (warp == 0) {
            int j = lane;
            float i_ = hsig (ZS[j]      + CVEC[j]);
            float f_ = hsig (ZS[32 + j] + CVEC[32 + j]);
            float g_ = tanh_fast(ZS[64 + j] + CVEC[64 + j]);
            float o_ = hsig (ZS[96 + j] + CVEC[96 + j]);
            cst_w = f_*cst_w + i_*g_;
            float h = o_ * tanh_fast(cst_w);
            if (t == LL - 1) out[b*DD + rank*32 + j] = h;
            float hop = h * ONX2[((t + 1) & 1)*32 + j];
            #pragma unroll
            for (int o = 16; o > 0; o >>= 1) hop += __shfl_xor_sync(0xffffffffu, hop, o);
            float hn = __shfl_xor_sync(0xffffffffu, h, 1);
            if ((j & 1) == 0) {
                #pragma unroll
                for (int q = 0; q < 4; q++)
                    st_async_f64(r_cb[q] + (CO_HWB + bufw*128u + rank*32u + (uint32_t)j)*4u,
                                 h, hn, r_cb[q] + CO_BHW*4u + (uint32_t)bufw*8u);
            }
            if (j == 0) {
                #pragma unroll
                for (int q = 0; q < 4; q++)
                    st_async_f32(r_cb[q] + (CO_HOB + rank)*4u,
                                 hop, r_cb[q] + CO_BHW*4u + (uint32_t)bufw*8u);
            }
        }
        // ---- warp2: reader gates -> o_{t+2} (deadline: next iteration)
        if (warp == 2 && t < LL - 1) {
            int j = lane;
            int xs = (t + 2) & 1;
            float i_ = hsig (ZSR[j]      + XWR[xs*128 + j]);
            float f_ = hsig (ZSR[32 + j] + XWR[xs*128 + 32 + j]);
            float g_ = tanh_fast(ZSR[64 + j] + XWR[xs*128 + 64 + j]);
            float o_ = hsig (ZSR[96 + j] + XWR[xs*128 + 96 + j]);
            cst_r = f_*cst_r + i_*g_;
            float hr = o_ * tanh_fast(cst_r);
            ONX2[((t + 2) & 1)*32 + j] = hr;
            float hn = __shfl_xor_sync(0xffffffffu, hr, 1);
            if ((j & 1) == 0) {
                #pragma unroll
                for (int q = 0; q < 4; q++)
                    st_async_f64(r_cb[q] + (CO_HRB + sl2*128u + rank*32u + (uint32_t)j)*4u,
                                 hr, hn, r_cb[q] + CO_BHR*4u + (uint32_t)sl2*8u);
            }
        }

        // ---- phase5a: snapshot z; dots with o_{t+1} (registers)
        float zold[4];
        #pragma unroll
        for (int li = 0; li < 4; li++) zold[li] = EE[r0 + li] * inv;

        float4 ov = reinterpret_cast<const float4*>(HRB + sl1*128)[lane];
        float dd[4];
        #pragma unroll
        for (int li = 0; li < 4; li++)
            dd[li] = m[li].x*ov.x + m[li].y*ov.y + m[li].z*ov.z + m[li].w*ov.w;
        #pragma unroll
        for (int ofs = 16, n = 4; ofs >= 8; ofs >>= 1, n >>= 1) {
            int half = n >> 1;
            bool side = (lane & ofs) != 0;
            #pragma unroll
            for (int i = 0; i < 2; i++) {
                if (i < half) {
                    float send = side ? dd[i] : dd[i + half];
                    float recv = __shfl_xor_sync(0xffffffffu, send, ofs);
                    dd[i] = (side ? dd[i + half] : dd[i]) + recv;
                }
            }
        }
        dd[0] += __shfl_xor_sync(0xffffffffu, dd[0], 4);
        dd[0] += __shfl_xor_sync(0xffffffffu, dd[0], 2);
        dd[0] += __shfl_xor_sync(0xffffffffu, dd[0], 1);

        mbar_wait(hwbarL[bufw], (t >> 1) & 1);

        // ---- phase5b: rank-1 score update; mem update; PA partials
        float ho = HOB[0] + HOB[1] + HOB[2] + HOB[3];
        if ((lane & 7) == 0) {
            int li = (lane >> 3) & 3;
            float z = zold[li];
            EE[r0 + li] = __expf(dd[0] + z*(ho - dd[0]));
        }
        __syncwarp();
        {
            float4 hv = reinterpret_cast<const float4*>(HWB + bufw*128)[lane];
            float4 pacc = make_float4(0.f, 0.f, 0.f, 0.f);
            float u = 0.f;
            #pragma unroll
            for (int li = 0; li < 4; li++) {
                float e = EE[r0 + li], z = zold[li];
                float w = e - e*z;           // e(1-z)
                pacc.x = fmaf(w, m[li].x, pacc.x);
                pacc.y = fmaf(w, m[li].y, pacc.y);
                pacc.z = fmaf(w, m[li].z, pacc.z);
                pacc.w = fmaf(w, m[li].w, pacc.w);
                u += e*z;
                m[li].x = fmaf(z, hv.x - m[li].x, m[li].x);
                m[li].y = fmaf(z, hv.y - m[li].y, m[li].y);
                m[li].z = fmaf(z, hv.z - m[li].z, m[li].z);
                m[li].w = fmaf(z, hv.w - m[li].w, m[li].w);
            }
            pacc.x = fmaf(u, hv.x, pacc.x);
            pacc.y = fmaf(u, hv.y, pacc.y);
            pacc.z = fmaf(u, hv.z, pacc.z);
            pacc.w = fmaf(u, hv.w, pacc.w);
            PA4[warp*32 + lane] = pacc;
        }
        __syncthreads();                              // SF
    }
    CLUSTER_SYNC_();
}

// ---------------------------------------------------------------------------
extern "C" void kernel_launch(void* const* d_in, const int* in_sizes, int n_in,
                              void* d_out, int out_size)
{
    const float* x  = (const float*)d_in[0];
    const float* Wr = (const float*)d_in[1];
    const float* Ur = (const float*)d_in[2];
    const float* br = (const float*)d_in[3];
    const float* Ww = (const float*)d_in[4];
    const float* Uw = (const float*)d_in[5];
    const float* bw = (const float*)d_in[6];
    const float* Wc = (const float*)d_in[7];
    const float* bc = (const float*)d_in[8];
    float* out = (float*)d_out;
    (void)in_sizes; (void)n_in; (void)out_size;

    void* p_xw;
    cudaGetSymbolAddress(&p_xw, g_xw);

    cudaFuncSetAttribute(fused_kernel,
                         cudaFuncAttributeMaxDynamicSharedMemorySize,
                         M_TOT * (int)sizeof(float));

    dim3 gdim(GG/64, (BB*LL)/64);

    // 0) xw = x @ Wr + br
    gemm_k128_n512<<<gdim, 256>>>(x, Wr, br, (float*)p_xw);
    // 1) fold weights: W2T (Uw,F), ET, URt, cvec
    prep_EF<<<DD, 512>>>(Wc, Ww, bc, bw, Uw, Ur);
    // 2) fused scan: reader 2 steps ahead, gates off critical path
    fused_kernel<<<4*BB, 512, M_TOT * (int)sizeof(float)>>>(x, out);
}

// round 17
// speedup vs baseline: 1.6495x; 1.6495x over previous
#include <cuda_runtime.h>
#include <cuda_fp16.h>
#include <math.h>
#include <stdint.h>

#define BB 32
#define LL 256
#define DD 128
#define GG 512

__device__ float g_xw  [BB*LL*GG];   // x @ Wr + br
// fp16, transposed, rank-sliced, gate-permuted weights:
// c = g*32 + jj  <->  global col = g*128 + r*32 + jj
__device__ __align__(16) __half g_W2Th[4*128*256];  // k: 0..127 Uw, 128..255 F
__device__ __align__(16) __half g_ETh [4*128*128];  // E = Wc_top@Ww
__device__ __align__(16) __half g_URh [4*128*128];  // Ur
__device__ float g_cvec[GG];                        // bc@Ww + bw

__device__ __forceinline__ float hsig(float x) {
    return fminf(fmaxf(0.2f*x + 0.5f, 0.0f), 1.0f);
}
__device__ __forceinline__ float tanh_fast(float x) {
    float e = __expf(fminf(2.0f*x, 80.0f));
    return 1.0f - __fdividef(2.0f, e + 1.0f);
}
__device__ __forceinline__ uint32_t smem_u32(const void* p) {
    uint32_t a;
    asm("{ .reg .u64 t; cvta.to.shared.u64 t, %1; cvt.u32.u64 %0, t; }" : "=r"(a) : "l"(p));
    return a;
}
__device__ __forceinline__ uint32_t ctarank() {
    uint32_t r; asm("mov.u32 %0, %%cluster_ctarank;" : "=r"(r)); return r;
}
__device__ __forceinline__ uint32_t mapa_u32(uint32_t a, uint32_t rk) {
    uint32_t o; asm("mapa.shared::cluster.u32 %0, %1, %2;" : "=r"(o) : "r"(a), "r"(rk)); return o;
}
__device__ __forceinline__ void mbar_init(uint32_t a, uint32_t cnt) {
    asm volatile("mbarrier.init.shared.b64 [%0], %1;" :: "r"(a), "r"(cnt) : "memory");
}
__device__ __forceinline__ void mbar_arrive_expect(uint32_t a, uint32_t tx) {
    asm volatile("mbarrier.arrive.expect_tx.shared.b64 _, [%0], %1;" :: "r"(a), "r"(tx) : "memory");
}
__device__ __forceinline__ void mbar_wait(uint32_t a, uint32_t parity) {
    uint32_t done;
    asm volatile("{\n\t.reg .pred p;\n\t"
        "mbarrier.try_wait.parity.acquire.cta.shared::cta.b64 p, [%1], %2;\n\t"
        "selp.b32 %0, 1, 0, p;\n\t}" : "=r"(done) : "r"(a), "r"(parity) : "memory");
    if (!done) {
        asm volatile("{\n\t.reg .pred P1;\n\tWL_%=:\n\t"
            "mbarrier.try_wait.parity.acquire.cta.shared::cta.b64 P1, [%0], %1, 0x989680;\n\t"
            "@P1 bra.uni WD_%=;\n\tbra.uni WL_%=;\n\tWD_%=:\n\t}"
            :: "r"(a), "r"(parity) : "memory");
    }
}
__device__ __forceinline__ void st_async_f32(uint32_t ra, float v, uint32_t rmb) {
    asm volatile("st.async.shared::cluster.mbarrier::complete_tx::bytes.b32 [%0], %1, [%2];"
                 :: "r"(ra), "r"(__float_as_uint(v)), "r"(rmb) : "memory");
}
__device__ __forceinline__ void st_async_f64(uint32_t ra, float a, float b, uint32_t rmb) {
    unsigned long long v = ((unsigned long long)__float_as_uint(b) << 32) | __float_as_uint(a);
    asm volatile("st.async.shared::cluster.mbarrier::complete_tx::bytes.b64 [%0], %1, [%2];"
                 :: "r"(ra), "l"(v), "r"(rmb) : "memory");
}
#define CLUSTER_SYNC_() do { \
    asm volatile("barrier.cluster.arrive.aligned;" ::: "memory"); \
    asm volatile("barrier.cluster.wait.aligned;" ::: "memory"); } while (0)
#define BAR_ARRIVE(id,cnt) asm volatile("bar.arrive %0, %1;" :: "r"(id), "r"(cnt) : "memory")
#define BAR_SYNC(id,cnt)   asm volatile("bar.sync %0, %1;"   :: "r"(id), "r"(cnt) : "memory")

// consumer parity for o_j arriving via hr ring slot j%3 (first bar uses: slot0:j=3, slot1:j=1, slot2:j=2)
__device__ __forceinline__ int hr_par(int j) {
    int s = j % 3;
    int base = (s == 0) ? 3 : s;
    return ((j - base) / 3) & 1;
}

__device__ __forceinline__ void red8_store(float* p, int lane, float* dst) {
    #pragma unroll
    for (int ofs = 16, n = 8; ofs >= 4; ofs >>= 1, n >>= 1) {
        int half = n >> 1;
        bool side = (lane & ofs) != 0;
        #pragma unroll
        for (int i = 0; i < 4; i++) {
            if (i < half) {
                float send = side ? p[i] : p[i + half];
                float recv = __shfl_xor_sync(0xffffffffu, send, ofs);
                p[i] = (side ? p[i + half] : p[i]) + recv;
            }
        }
    }
    p[0] += __shfl_xor_sync(0xffffffffu, p[0], 2);
    p[0] += __shfl_xor_sync(0xffffffffu, p[0], 1);
    if ((lane & 3) == 0) dst[(lane >> 2) & 7] = p[0];
}

__device__ __forceinline__ float dot4_h(uint2 w, float4 hv) {
    float2 a = __half22float2(*reinterpret_cast<__half2*>(&w.x));
    float2 b = __half22float2(*reinterpret_cast<__half2*>(&w.y));
    return hv.x*a.x + hv.y*a.y + hv.z*b.x + hv.w*b.y;
}

// ---------------- GEMM: C[M,512] = A[M,128] @ W[128,512] + bias ------------
__global__ void __launch_bounds__(256) gemm_k128_n512(
        const float* __restrict__ A, const float* __restrict__ W,
        const float* __restrict__ bias, float* __restrict__ C)
{
    __shared__ __align__(16) float As[64][68];
    __shared__ __align__(16) float Ws[64][64];
    int tid = threadIdx.x, tx = tid & 15, ty = tid >> 4;
    int n0 = blockIdx.x * 64;
    long r0 = (long)blockIdx.y * 64;
    float acc[4][4] = {};
    for (int kc = 0; kc < 128; kc += 64) {
        #pragma unroll
        for (int i = 0; i < 4; i++) {
            int f = tid + i*256, row = f >> 4, c4 = (f & 15) * 4;
            *reinterpret_cast<float4*>(&As[row][c4]) =
                *reinterpret_cast<const float4*>(A + (r0 + row)*128 + kc + c4);
            *reinterpret_cast<float4*>(&Ws[row][c4]) =
                *reinterpret_cast<const float4*>(W + (long)(kc + row)*GG + n0 + c4);
        }
        __syncthreads();
        #pragma unroll
        for (int k = 0; k < 64; k++) {
            float4 wv = *reinterpret_cast<const float4*>(&Ws[k][tx*4]);
            #pragma unroll
            for (int i = 0; i < 4; i++) {
                float a = As[ty*4 + i][k];
                acc[i][0] += a*wv.x; acc[i][1] += a*wv.y;
                acc[i][2] += a*wv.z; acc[i][3] += a*wv.w;
            }
        }
        __syncthreads();
    }
    int col = n0 + tx*4;
    float4 bv = *reinterpret_cast<const float4*>(bias + col);
    #pragma unroll
    for (int i = 0; i < 4; i++) {
        float4 o;
        o.x = acc[i][0] + bv.x; o.y = acc[i][1] + bv.y;
        o.z = acc[i][2] + bv.z; o.w = acc[i][3] + bv.w;
        *reinterpret_cast<float4*>(C + (r0 + ty*4 + i)*GG + col) = o;
    }
}

// ---------------- prep: fp16 transposed W2T/ET/URt, cvec -------------------
__global__ void __launch_bounds__(512) prep_EF(
        const float* __restrict__ Wc, const float* __restrict__ Ww,
        const float* __restrict__ bc, const float* __restrict__ bw,
        const float* __restrict__ Uw, const float* __restrict__ Ur)
{
    __shared__ float st[DD], sb[DD], sc[DD];
    int d = blockIdx.x, j = threadIdx.x;
    if (j < DD) { st[j] = Wc[d*DD + j]; sb[j] = Wc[(DD + d)*DD + j]; sc[j] = bc[j]; }
    __syncthreads();
    float e = 0.f, f = 0.f, cv = 0.f;
    #pragma unroll 8
    for (int c = 0; c < DD; c++) {
        float w = Ww[c*GG + j];
        e += st[c]*w; f += sb[c]*w; cv += sc[c]*w;
    }
    int g = j >> 7, r = (j >> 5) & 3, jj = j & 31;
    int c = g*32 + jj;
    g_W2Th[(r*128 + c)*256 + d]       = __float2half(Uw[d*GG + j]);
    g_W2Th[(r*128 + c)*256 + 128 + d] = __float2half(f);
    g_ETh [(r*128 + c)*128 + d]       = __float2half(e);
    g_URh [(r*128 + c)*128 + d]       = __float2half(Ur[d*GG + j]);
    if (d == 0) g_cvec[j] = cv + bw[j];
}

// ---------------- fused kernel: reader 2 ahead + writer, min-critical-path -
// smem float offsets
#define M_W2   0        // UwF half [128][256]   (16384)
#define M_EU   16384    // E half [128][128]     (8192)
#define M_UR   24576    // Ur half [128][128]    (8192)
#define M_PA   32768    // [16][128]             (2048)
#define M_CVEC 34816    // [128]
#define M_ZS   34944    // [128]
#define M_ZSR  35072    // [128]
#define M_XWR  35200    // [2][128]
#define M_EE   35456    // [64]
#define M_ONX2 35520    // [2][32]
#define M_COMM 35584    // comm block below (even offset)
// comm block (float offsets relative to M_COMM)
#define CO_MRTB 0       // [4][128]
#define CO_HRB  512     // [3][128] o ring
#define CO_HWB  896     // [2][128] h ring
#define CO_SB   1152    // [4]
#define CO_HOB  1156    // [4]
#define CO_BMRT 1160    // 1 bar
#define CO_BHW  1162    // 2 bars
#define CO_BHR  1166    // 3 bars
#define C_TOT   1172
#define M_TOT  (M_COMM + C_TOT)

__global__ void __launch_bounds__(512, 1) __cluster_dims__(4, 1, 1)
fused_kernel(const float* __restrict__ x, float* __restrict__ out)
{
    extern __shared__ __align__(16) float sm[];
    float* PA   = sm + M_PA;
    float* CVEC = sm + M_CVEC;
    float* ZS   = sm + M_ZS;
    float* ZSR  = sm + M_ZSR;
    float* XWR  = sm + M_XWR;
    float* EE   = sm + M_EE;
    float* ONX2 = sm + M_ONX2;
    float* CM   = sm + M_COMM;
    float* MRTB = CM + CO_MRTB;
    float* HRB  = CM + CO_HRB;
    float* HWB  = CM + CO_HWB;
    float* SB   = CM + CO_SB;
    float* HOB  = CM + CO_HOB;
    const uint2* W2u = reinterpret_cast<const uint2*>(sm + M_W2);  // 64 uint2/col
    const uint2* EUu = reinterpret_cast<const uint2*>(sm + M_EU);  // 32 uint2/col
    const uint2* URu = reinterpret_cast<const uint2*>(sm + M_UR);  // 32 uint2/col

    int tid = threadIdx.x, lane = tid & 31, warp = tid >> 5;
    uint32_t rank = ctarank();
    int b = blockIdx.x >> 2;
    int r0 = warp*4;

    uint32_t mrt_barL = smem_u32(CM + CO_BMRT);
    uint32_t hwbarL[2] = { smem_u32(CM + CO_BHW), smem_u32(CM + CO_BHW + 2) };
    uint32_t hrbarL[3] = { smem_u32(CM + CO_BHR), smem_u32(CM + CO_BHR + 2),
                           smem_u32(CM + CO_BHR + 4) };
    if (tid == 0) {
        mbar_init(mrt_barL, 1);
        mbar_init(hwbarL[0], 1); mbar_init(hwbarL[1], 1);
        mbar_init(hrbarL[0], 1); mbar_init(hrbarL[1], 1); mbar_init(hrbarL[2], 1);
    }

    const float* xwb = g_xw + (long)b*LL*GG;

    // weight slices -> smem (fp16)
    {
        uint4* dst = reinterpret_cast<uint4*>(sm + M_W2);
        const uint4* src = reinterpret_cast<const uint4*>(g_W2Th) + (long)rank*4096;
        for (int i = tid; i < 4096; i += 512) dst[i] = src[i];
        uint4* dstE = reinterpret_cast<uint4*>(sm + M_EU);
        const uint4* srcE = reinterpret_cast<const uint4*>(g_ETh) + (long)rank*2048;
        for (int i = tid; i < 2048; i += 512) dstE[i] = srcE[i];
        uint4* dstU = reinterpret_cast<uint4*>(sm + M_UR);
        const uint4* srcU = reinterpret_cast<const uint4*>(g_URh) + (long)rank*2048;
        for (int i = tid; i < 2048; i += 512) dstU[i] = srcU[i];
    }
    // mem slice -> REGISTERS: warp owns rows r0..r0+3 (global rows rank*64+..)
    float4 m[4];
    {
        const float* xb = x + ((long)b*LL + rank*64)*DD;
        #pragma unroll
        for (int li = 0; li < 4; li++)
            m[li] = *reinterpret_cast<const float4*>(xb + (r0 + li)*DD + lane*4);
    }
    if (tid < 256) HWB[tid] = 0.f;
    if (tid < 128) {
        // reader step 0 (h=0): o_0 full vector (computed locally by every CTA)
        float zi = xwb[tid], zg = xwb[256 + tid], zo = xwb[384 + tid];
        float c0 = hsig(zi) * tanh_fast(zg);
        float o0 = hsig(zo) * tanh_fast(c0);
        HRB[tid] = o0;         // ring slot 0
        ZSR[tid] = c0;         // stash c_r(0) for warp2 pickup
        CVEC[tid] = g_cvec[(tid >> 5)*128 + rank*32 + (tid & 31)];
    } else if (tid < 256) {
        int i = tid - 128;     // XWR slot 0 = xw step 2 (read by warp2 at t=0)
        XWR[i] = xwb[2*GG + (i >> 5)*128 + rank*32 + (i & 31)];
    }
    float cst_w = 0.f, cst_r = 0.f;
    __syncthreads();
    CLUSTER_SYNC_();

    // single comm-base address per peer (q=3 -> self)
    uint32_t r_cb[4];
    #pragma unroll
    for (int q = 0; q < 4; q++)
        r_cb[q] = mapa_u32(smem_u32(CM), (rank + 1 + q) & 3);

    float4* PA4  = reinterpret_cast<float4*>(PA);
    const float2* PA2 = reinterpret_cast<const float2*>(PA);
    const float4* MRTB4 = reinterpret_cast<const float4*>(MRTB);

    // ---- bootstrap: reader step 1 -> o_1 (ring slot 1) --------------------
    if (tid == 0) mbar_arrive_expect(hrbarL[1], 512);
    {
        float4 o0v = reinterpret_cast<const float4*>(HRB)[lane];
        float accB[8];
        #pragma unroll
        for (int i = 0; i < 8; i++)
            accB[i] = dot4_h(URu[(warp*8 + i)*32 + lane], o0v);
        red8_store(accB, lane, ZS + warp*8);
    }
    __syncthreads();
    if (warp == 2) {
        int j = lane;
        cst_r = ZSR[rank*32 + j];              // c_r(0)
        float i_ = hsig (ZS[j]      + xwb[GG + 0*128 + rank*32 + j]);
        float f_ = hsig (ZS[32 + j] + xwb[GG + 1*128 + rank*32 + j]);
        float g_ = tanh_fast(ZS[64 + j] + xwb[GG + 2*128 + rank*32 + j]);
        float o_ = hsig (ZS[96 + j] + xwb[GG + 3*128 + rank*32 + j]);
        cst_r = f_*cst_r + i_*g_;
        float hr = o_ * tanh_fast(cst_r);      // o_1 local dims
        ONX2[32 + j] = hr;                     // ONX slot 1
        float hn = __shfl_xor_sync(0xffffffffu, hr, 1);
        if ((j & 1) == 0) {
            #pragma unroll
            for (int q = 0; q < 4; q++)
                st_async_f64(r_cb[q] + (CO_HRB + 128u + rank*32u + (uint32_t)j)*4u,
                             hr, hn, r_cb[q] + CO_BHR*4u + 1u*8u);
        }
    }
    // ---- initial scores s_0 from o_0 (registers) -> EE, PA ----------------
    {
        float4 ov = reinterpret_cast<const float4*>(HRB)[lane];
        float pr_[4];
        #pragma unroll
        for (int li = 0; li < 4; li++)
            pr_[li] = m[li].x*ov.x + m[li].y*ov.y + m[li].z*ov.z + m[li].w*ov.w;
        #pragma unroll
        for (int ofs = 16, n = 4; ofs >= 8; ofs >>= 1, n >>= 1) {
            int half = n >> 1;
            bool side = (lane & ofs) != 0;
            #pragma unroll
            for (int i = 0; i < 2; i++) {
                if (i < half) {
                    float send = side ? pr_[i] : pr_[i + half];
                    float recv = __shfl_xor_sync(0xffffffffu, send, ofs);
                    pr_[i] = (side ? pr_[i + half] : pr_[i]) + recv;
                }
            }
        }
        pr_[0] += __shfl_xor_sync(0xffffffffu, pr_[0], 4);
        pr_[0] += __shfl_xor_sync(0xffffffffu, pr_[0], 2);
        pr_[0] += __shfl_xor_sync(0xffffffffu, pr_[0], 1);
        if ((lane & 7) == 0) EE[r0 + ((lane >> 3) & 3)] = __expf(pr_[0]);
        __syncwarp();
        float4 pacc = make_float4(0.f, 0.f, 0.f, 0.f);
        #pragma unroll
        for (int li = 0; li < 4; li++) {
            float e = EE[r0 + li];
            pacc.x = fmaf(e, m[li].x, pacc.x);
            pacc.y = fmaf(e, m[li].y, pacc.y);
            pacc.z = fmaf(e, m[li].z, pacc.z);
            pacc.w = fmaf(e, m[li].w, pacc.w);
        }
        PA4[warp*32 + lane] = pacc;
    }
    __syncthreads();

    for (int t = 0; t < LL; t++) {
        int sl0 = t % 3, sl1 = (t + 1) % 3, sl2 = (t + 2) % 3;
        int bufw = t & 1;
        if (tid == 0) {
            mbar_arrive_expect(mrt_barL, 2064);          // 4 x (512 + 4)
            mbar_arrive_expect(hwbarL[bufw], 528);       // 4 x (128 + 4)
            if (t < LL - 1) mbar_arrive_expect(hrbarL[sl2], 512);
        }
        // ---- o_{t+1} arrival (sent an iteration ago -> ~free)
        mbar_wait(hrbarL[sl1], hr_par(t + 1));

        // ---- sends + prefetch
        if (tid < 64) {
            float2 p = make_float2(0.f, 0.f);
            #pragma unroll
            for (int w = 0; w < 16; w++) {
                float2 v = PA2[w*64 + tid];
                p.x += v.x; p.y += v.y;
            }
            #pragma unroll
            for (int q = 0; q < 4; q++)
                st_async_f64(r_cb[q] + (CO_MRTB + rank*128u + 2u*(uint32_t)tid)*4u,
                             p.x, p.y, r_cb[q] + CO_BMRT*4u);
        } else if (tid >= 96 && tid < 128) {
            float v = EE[lane] + EE[32 + lane];
            #pragma unroll
            for (int o = 16; o > 0; o >>= 1) v += __shfl_xor_sync(0xffffffffu, v, o);
            if (lane == 0) {
                #pragma unroll
                for (int q = 0; q < 4; q++)
                    st_async_f32(r_cb[q] + (CO_SB + rank)*4u, v, r_cb[q] + CO_BMRT*4u);
            }
        } else if (tid >= 128 && tid < 192) {
            int i = (tid - 128)*2;
            int tn3 = (t + 3 < LL) ? t + 3 : LL - 1;
            int s = (t + 3) & 1;
            XWR[s*128 + i]     = xwb[tn3*GG + (i >> 5)*128 + rank*32 + (i & 31)];
            XWR[s*128 + i + 1] = xwb[tn3*GG + ((i+1) >> 5)*128 + rank*32 + ((i+1) & 31)];
        }
        // ---- GEMVs: reader (o_{t+1}), writer Uw(h_w) + E(o_t)
        float accR[8], acc[8];
        {
            float4 ov1 = reinterpret_cast<const float4*>(HRB + sl1*128)[lane];
            float4 ov0 = reinterpret_cast<const float4*>(HRB + sl0*128)[lane];
            float4 hwv = reinterpret_cast<const float4*>(HWB + (bufw ^ 1)*128)[lane];
            #pragma unroll
            for (int i = 0; i < 8; i++) {
                int c = warp*8 + i;
                accR[i] = dot4_h(URu[c*32 + lane], ov1);
                acc[i]  = dot4_h(W2u[c*64 + lane], hwv) + dot4_h(EUu[c*32 + lane], ov0);
            }
            red8_store(accR, lane, ZSR + warp*8);
        }
        // ---- F-half GEMV on unnormalized P (deferred normalization)
        mbar_wait(mrt_barL, t & 1);
        float inv = 1.0f / (SB[0] + SB[1] + SB[2] + SB[3]);
        {
            float4 mvP = MRTB4[lane];
            float4 v1 = MRTB4[32 + lane], v2 = MRTB4[64 + lane], v3 = MRTB4[96 + lane];
            mvP.x += v1.x + v2.x + v3.x;
            mvP.y += v1.y + v2.y + v3.y;
            mvP.z += v1.z + v2.z + v3.z;
            mvP.w += v1.w + v2.w + v3.w;
            #pragma unroll
            for (int i = 0; i < 8; i++) {
                float f = dot4_h(W2u[(warp*8 + i)*64 + 32 + lane], mvP);
                acc[i] = fmaf(f, inv, acc[i]);
            }
            red8_store(acc, lane, ZS + warp*8);
        }
        // ---- named barrier: 14 warps arrive, warps 0 & 2 sync
        if (warp == 0 || warp == 2) BAR_SYNC(1, 512); else BAR_ARRIVE(1, 512);

        // ---- warp0: writer gates + h/ho sends
        if (warp == 0) {
            int j = lane;
            float i_ = hsig (ZS[j]      + CVEC[j]);
            float f_ = hsig (ZS[32 + j] + CVEC[32 + j]);
            float g_ = tanh_fast(ZS[64 + j] + CVEC[64 + j]);
            float o_ = hsig (ZS[96 + j] + CVEC[96 + j]);
            cst_w = f_*cst_w + i_*g_;
            float h = o_ * tanh_fast(cst_w);
            if (t == LL - 1) out[b*DD + rank*32 + j] = h;
            float hop = h * ONX2[((t + 1) & 1)*32 + j];
            #pragma unroll
            for (int o = 16; o > 0; o >>= 1) hop += __shfl_xor_sync(0xffffffffu, hop, o);
            float hn = __shfl_xor_sync(0xffffffffu, h, 1);
            if ((j & 1) == 0) {
                #pragma unroll
                for (int q = 0; q < 4; q++)
                    st_async_f64(r_cb[q] + (CO_HWB + bufw*128u + rank*32u + (uint32_t)j)*4u,
                                 h, hn, r_cb[q] + CO_BHW*4u + (uint32_t)bufw*8u);
            }
            if (j == 0) {
                #pragma unroll
                for (int q = 0; q < 4; q++)
                    st_async_f32(r_cb[q] + (CO_HOB + rank)*4u,
                                 hop, r_cb[q] + CO_BHW*4u + (uint32_t)bufw*8u);
            }
        }
        // ---- warp2: reader gates -> o_{t+2} (deadline: next iteration)
        if (warp == 2 && t < LL - 1) {
            int j = lane;
            int xs = (t + 2) & 1;
            float i_ = hsig (ZSR[j]      + XWR[xs*128 + j]);
            float f_ = hsig (ZSR[32 + j] + XWR[xs*128 + 32 + j]);
            float g_ = tanh_fast(ZSR[64 + j] + XWR[xs*128 + 64 + j]);
            float o_ = hsig (ZSR[96 + j] + XWR[xs*128 + 96 + j]);
            cst_r = f_*cst_r + i_*g_;
            float hr = o_ * tanh_fast(cst_r);
            ONX2[((t + 2) & 1)*32 + j] = hr;
            float hn = __shfl_xor_sync(0xffffffffu, hr, 1);
            if ((j & 1) == 0) {
                #pragma unroll
                for (int q = 0; q < 4; q++)
                    st_async_f64(r_cb[q] + (CO_HRB + sl2*128u + rank*32u + (uint32_t)j)*4u,
                                 hr, hn, r_cb[q] + CO_BHR*4u + (uint32_t)sl2*8u);
            }
        }

        // ---- phase5a: snapshot z; dots with o_{t+1} (registers)
        float zold[4];
        #pragma unroll
        for (int li = 0; li < 4; li++) zold[li] = EE[r0 + li] * inv;

        float4 ov = reinterpret_cast<const float4*>(HRB + sl1*128)[lane];
        float dd[4];
        #pragma unroll
        for (int li = 0; li < 4; li++)
            dd[li] = m[li].x*ov.x + m[li].y*ov.y + m[li].z*ov.z + m[li].w*ov.w;
        #pragma unroll
        for (int ofs = 16, n = 4; ofs >= 8; ofs >>= 1, n >>= 1) {
            int half = n >> 1;
            bool side = (lane & ofs) != 0;
            #pragma unroll
            for (int i = 0; i < 2; i++) {
                if (i < half) {
                    float send = side ? dd[i] : dd[i + half];
                    float recv = __shfl_xor_sync(0xffffffffu, send, ofs);
                    dd[i] = (side ? dd[i + half] : dd[i]) + recv;
                }
            }
        }
        dd[0] += __shfl_xor_sync(0xffffffffu, dd[0], 4);
        dd[0] += __shfl_xor_sync(0xffffffffu, dd[0], 2);
        dd[0] += __shfl_xor_sync(0xffffffffu, dd[0], 1);

        mbar_wait(hwbarL[bufw], (t >> 1) & 1);

        // ---- phase5b: rank-1 score update; mem update; PA partials
        float ho = HOB[0] + HOB[1] + HOB[2] + HOB[3];
        if ((lane & 7) == 0) {
            int li = (lane >> 3) & 3;
            float z = zold[li];
            EE[r0 + li] = __expf(dd[0] + z*(ho - dd[0]));
        }
        __syncwarp();
        {
            float4 hv = reinterpret_cast<const float4*>(HWB + bufw*128)[lane];
            float4 pacc = make_float4(0.f, 0.f, 0.f, 0.f);
            float u = 0.f;
            #pragma unroll
            for (int li = 0; li < 4; li++) {
                float e = EE[r0 + li], z = zold[li];
                float w = e - e*z;           // e(1-z)
                pacc.x = fmaf(w, m[li].x, pacc.x);
                pacc.y = fmaf(w, m[li].y, pacc.y);
                pacc.z = fmaf(w, m[li].z, pacc.z);
                pacc.w = fmaf(w, m[li].w, pacc.w);
                u += e*z;
                m[li].x = fmaf(z, hv.x - m[li].x, m[li].x);
                m[li].y = fmaf(z, hv.y - m[li].y, m[li].y);
                m[li].z = fmaf(z, hv.z - m[li].z, m[li].z);
                m[li].w = fmaf(z, hv.w - m[li].w, m[li].w);
            }
            pacc.x = fmaf(u, hv.x, pacc.x);
            pacc.y = fmaf(u, hv.y, pacc.y);
            pacc.z = fmaf(u, hv.z, pacc.z);
            pacc.w = fmaf(u, hv.w, pacc.w);
            PA4[warp*32 + lane] = pacc;
        }
        __syncthreads();                              // SF
    }
    CLUSTER_SYNC_();
}

// ---------------------------------------------------------------------------
extern "C" void kernel_launch(void* const* d_in, const int* in_sizes, int n_in,
                              void* d_out, int out_size)
{
    const float* x  = (const float*)d_in[0];
    const float* Wr = (const float*)d_in[1];
    const float* Ur = (const float*)d_in[2];
    const float* br = (const float*)d_in[3];
    const float* Ww = (const float*)d_in[4];
    const float* Uw = (const float*)d_in[5];
    const float* bw = (const float*)d_in[6];
    const float* Wc = (const float*)d_in[7];
    const float* bc = (const float*)d_in[8];
    float* out = (float*)d_out;
    (void)in_sizes; (void)n_in; (void)out_size;

    void* p_xw;
    cudaGetSymbolAddress(&p_xw, g_xw);

    cudaFuncSetAttribute(fused_kernel,
                         cudaFuncAttributeMaxDynamicSharedMemorySize,
                         M_TOT * (int)sizeof(float));

    dim3 gdim(GG/64, (BB*LL)/64);

    // 0) xw = x @ Wr + br
    gemm_k128_n512<<<gdim, 256>>>(x, Wr, br, (float*)p_xw);
    // 1) fold weights: W2T (Uw,F), ET, URt, cvec
    prep_EF<<<DD, 512>>>(Wc, Ww, bc, bw, Uw, Ur);
    // 2) fused scan: reader 2 steps ahead, gates off critical path
    fused_kernel<<<4*BB, 512, M_TOT * (int)sizeof(float)>>>(x, out);
}